// round 7
// baseline (speedup 1.0000x reference)
#include <cuda_runtime.h>
#include <cstdint>

#define N_PRE   1024
#define N_POST  2048
#define SEQ_T   4096
#define DECAY   0.9f
#define V_TH    1.0f
#define MAXA    192            // max stored actives/t (mean 102, sd 9.6); leaves >=8 sentinel slots
#define GPAD    33             // smem row pitch (odd => conflict-free transpose store AND row load)
#define TCHUNK  128            // timesteps per gather CTA

// ---------------- device scratch (no cudaMalloc allowed) --------------------------------
__device__ int   g_cnt[SEQ_T];                          // exact active count per timestep
__device__ int   g_idx[SEQ_T * MAXA];                   // active pre indices, sentinel-padded
__device__ float g_cur[(size_t)SEQ_T * N_POST];         // currents [t][n], 32 MB

// ---------------- kernel 1: build per-timestep active index lists ------------------------
// One thread per t, 128 blocks x 32 threads. Pads each list to a multiple of 8 with
// sentinel p = N_PRE, PLUS 8 extra sentinels so the gather can prefetch unguarded.
__global__ void __launch_bounds__(32) k_build_lists(const float* __restrict__ stim) {
    const int t = blockIdx.x * 32 + threadIdx.x;
    int cnt = 0;
    int* lp = &g_idx[t * MAXA];
#pragma unroll 8
    for (int p = 0; p < N_PRE; p++) {
        if (stim[(size_t)p * SEQ_T + t] > 0.5f) {
            if (cnt < MAXA - 16) lp[cnt] = p;
            cnt++;
        }
    }
    cnt = cnt < MAXA - 16 ? cnt : MAXA - 16;            // cap: 176 >> mean+7sd
    const int c8 = (cnt + 7) & ~7;
    for (int j = cnt; j < c8 + 8; j++) lp[j] = N_PRE;   // sentinels (zero row in smem)
    g_cnt[t] = cnt;
}

// ---------------- kernel 2: smem-staged sparse gather v2 ---------------------------------
// grid (64 n-slices, 32 t-chunks) = 2048 CTAs (1/SM, ~14 waves), block 256 (8 warps).
// Stage W[p][32-n slice] transposed in smem (conflict-free both ways), then each warp
// sums active rows for its timesteps via pure conflict-free LDS. Moves 3.34 GB of row
// traffic off the LTS cap (~7 KB/cyc chip, measured-saturated in R4) onto the smem
// crossbar (~19 KB/cyc chip). R3's latency failure is addressed with 16x more CTAs,
// 8-deep index prefetch, and sentinel-padded fixed-step loops.
__global__ void __launch_bounds__(256) k_gather(const float* __restrict__ W) {
    extern __shared__ float sw[];                       // [(N_PRE+8)][GPAD]
    const int n0 = blockIdx.x * 32;
    const int tb = blockIdx.y * TCHUNK;
    const int lane = threadIdx.x & 31;
    const int warp = threadIdx.x >> 5;

    // ---- stage W slice, transposed: sw[p][r] = W[n0+r][p] ----
    // (32,8) pattern: lane = p within chunk (coalesced LDG), STS lane-stride GPAD (odd).
    for (int pc = 0; pc < N_PRE; pc += 32) {
#pragma unroll
        for (int r0 = 0; r0 < 32; r0 += 8) {
            const float w = W[(size_t)(n0 + r0 + warp) * N_PRE + pc + lane];
            sw[(size_t)(pc + lane) * GPAD + (r0 + warp)] = w;
        }
    }
    // zero the sentinel rows (p = N_PRE .. N_PRE+7)
    for (int i = threadIdx.x; i < 8 * GPAD; i += 256)
        sw[(size_t)N_PRE * GPAD + i] = 0.f;
    __syncthreads();

    // ---- per-warp timestep loop: warp handles t = tb+warp, step 8 (16 timesteps) ----
    int c_cur = g_cnt[tb + warp];
    for (int t = tb + warp; t < tb + TCHUNK; t += 8) {
        // prefetch next timestep's count early
        const int tn = t + 8;
        const int c_nxt = (tn < tb + TCHUNK) ? g_cnt[tn] : 0;

        const int* __restrict__ lp = &g_idx[t * MAXA];
        const int c8 = (c_cur + 7) & ~7;

        float a0 = 0.f, a1 = 0.f, a2 = 0.f, a3 = 0.f;
        // first index batch (list always has >= c8+8 valid entries incl. sentinels)
        int p0 = lp[0], p1 = lp[1], p2 = lp[2], p3 = lp[3];
        int p4 = lp[4], p5 = lp[5], p6 = lp[6], p7 = lp[7];

        for (int j = 0; j < c8; j += 8) {
            // prefetch next batch (unguarded: sentinel tail makes it safe)
            const int q0 = lp[j + 8],  q1 = lp[j + 9],  q2 = lp[j + 10], q3 = lp[j + 11];
            const int q4 = lp[j + 12], q5 = lp[j + 13], q6 = lp[j + 14], q7 = lp[j + 15];

            a0 += sw[p0 * GPAD + lane];
            a1 += sw[p1 * GPAD + lane];
            a2 += sw[p2 * GPAD + lane];
            a3 += sw[p3 * GPAD + lane];
            a0 += sw[p4 * GPAD + lane];
            a1 += sw[p5 * GPAD + lane];
            a2 += sw[p6 * GPAD + lane];
            a3 += sw[p7 * GPAD + lane];

            p0 = q0; p1 = q1; p2 = q2; p3 = q3;
            p4 = q4; p5 = q5; p6 = q6; p7 = q7;
        }
        g_cur[(size_t)t * N_POST + n0 + lane] = (a0 + a1) + (a2 + a3);
        c_cur = c_nxt;
    }
}

// ---------------- kernel 3: LIF scan, spill-free static 3-stage pipeline (unchanged R4) --
#define TT 16
__global__ void __launch_bounds__(32) k_lif_scan(float* __restrict__ out) {
    const int n = blockIdx.x * 32 + threadIdx.x;
    float* __restrict__ out_s = out + (size_t)n * SEQ_T;
    float* __restrict__ out_v = out + (size_t)N_POST * SEQ_T + (size_t)n * SEQ_T;

    const int NT = SEQ_T / TT;                          // 256 tiles
    float buf[3][TT];

#pragma unroll
    for (int s = 0; s < 3; s++)
#pragma unroll
        for (int k = 0; k < TT; k++)
            buf[s][k] = g_cur[(size_t)(s * TT + k) * N_POST + n];

    float v = 0.f;
    for (int base = 0; base < NT; base += 3) {
#pragma unroll
        for (int s = 0; s < 3; s++) {
            const int tile = base + s;
            if (tile < NT) {
                float sb[TT], vb[TT];
#pragma unroll
                for (int k = 0; k < TT; k++) {
                    v = v * DECAY + buf[s][k];
                    const bool f = (v >= V_TH);
                    sb[k] = f ? 1.f : 0.f;
                    v = f ? 0.f : v;
                    vb[k] = v;
                }
                if (tile + 3 < NT) {
#pragma unroll
                    for (int k = 0; k < TT; k++)
                        buf[s][k] = g_cur[(size_t)((tile + 3) * TT + k) * N_POST + n];
                }
                const size_t o4 = (size_t)tile * (TT / 4);
#pragma unroll
                for (int q = 0; q < TT / 4; q++) {
                    ((float4*)out_s)[o4 + q] =
                        make_float4(sb[4 * q], sb[4 * q + 1], sb[4 * q + 2], sb[4 * q + 3]);
                    ((float4*)out_v)[o4 + q] =
                        make_float4(vb[4 * q], vb[4 * q + 1], vb[4 * q + 2], vb[4 * q + 3]);
                }
            }
        }
    }
}

// ---------------- launch --------------------------------------------------------------
extern "C" void kernel_launch(void* const* d_in, const int* in_sizes, int n_in,
                              void* d_out, int out_size) {
    const float* stim = (const float*)d_in[0];   // [N_PRE, SEQ_T]
    const float* W    = (const float*)d_in[1];   // [N_POST, N_PRE]
    if (n_in >= 2 && in_sizes[0] == N_POST * N_PRE && in_sizes[1] == N_PRE * SEQ_T) {
        const float* tmp = stim; stim = W; W = tmp;
    }
    float* out = (float*)d_out;

    const int GATHER_SMEM = (N_PRE + 8) * GPAD * (int)sizeof(float);   // 136,224 B
    static int smem_set = 0;
    if (!smem_set) {
        cudaFuncSetAttribute(k_gather, cudaFuncAttributeMaxDynamicSharedMemorySize, GATHER_SMEM);
        smem_set = 1;
    }

    k_build_lists<<<SEQ_T / 32, 32>>>(stim);
    k_gather<<<dim3(N_POST / 32, SEQ_T / TCHUNK), 256, GATHER_SMEM>>>(W);
    k_lif_scan<<<N_POST / 32, 32>>>(out);
}

// round 8
// speedup vs baseline: 3.0501x; 3.0501x over previous
#include <cuda_runtime.h>
#include <cstdint>

#define N_PRE   1024
#define N_POST  2048
#define SEQ_T   4096
#define DECAY   0.9f
#define V_TH    1.0f
#define MAXA    192            // max actives/t (mean 102, sd 9.6; 192 ~ 9 sigma)

// ---------------- device scratch (no cudaMalloc allowed) --------------------------------
__device__ float    g_WT[N_PRE * (size_t)N_POST];       // W transposed: [p][n], 8 MB
__device__ uint32_t g_bits[32 * SEQ_T];                 // spike bitmask [w][t], 512 KB
__device__ int      g_cnt[SEQ_T];                       // active count per timestep
__device__ int      g_idx[SEQ_T * MAXA];                // active pre indices (ascending p)
__device__ float    g_cur[(size_t)SEQ_T * N_POST];      // currents [t][n], 32 MB

// ---------------- kernel 1: transpose W [n][p] -> WT [p][n] ------------------------------
__global__ void k_transpose(const float* __restrict__ W) {
    __shared__ float tile[32][33];
    const int p0 = blockIdx.x * 32;
    const int n0 = blockIdx.y * 32;
    const int tx = threadIdx.x, ty = threadIdx.y;   // block (32, 8)
#pragma unroll
    for (int i = 0; i < 32; i += 8)
        tile[ty + i][tx] = W[(size_t)(n0 + ty + i) * N_PRE + p0 + tx];
    __syncthreads();
#pragma unroll
    for (int i = 0; i < 32; i += 8)
        g_WT[(size_t)(p0 + ty + i) * N_POST + n0 + tx] = tile[tx][ty + i];
}

// ---------------- kernel 2a: stim -> bitmask, massively parallel -------------------------
// One thread per (t, word): 131072 threads. Lane-consecutive t => every load coalesced;
// 32 independent loads per thread (huge chip-wide MLP). Replaces the serial part of the
// old k_build_lists that cost 113us at 5.3% issue.
__global__ void __launch_bounds__(256) k_spike_bits(const float* __restrict__ stim) {
    const int idx = blockIdx.x * 256 + threadIdx.x;     // 512 blocks x 256
    const int w = idx >> 12;                            // 0..31
    const int t = idx & (SEQ_T - 1);
    uint32_t m = 0;
#pragma unroll
    for (int j = 0; j < 32; j++)
        m |= (stim[(size_t)(32 * w + j) * SEQ_T + t] > 0.5f) ? (1u << j) : 0u;
    g_bits[w * SEQ_T + t] = m;
}

// ---------------- kernel 2b: bitmask -> index lists (cheap serial part) ------------------
// One thread per t. 32 coalesced independent word loads, then ~102 ALU-only ffs
// extractions. Produces ascending-p lists identical to the previous build.
__global__ void __launch_bounds__(32) k_lists_from_bits() {
    const int t = blockIdx.x * 32 + threadIdx.x;        // 128 blocks x 32
    uint32_t wbuf[32];
#pragma unroll
    for (int w = 0; w < 32; w++)
        wbuf[w] = g_bits[w * SEQ_T + t];                // coalesced at each w
    int cnt = 0;
    int* lp = &g_idx[t * MAXA];
#pragma unroll
    for (int w = 0; w < 32; w++) {
        uint32_t m = wbuf[w];
        while (m) {
            const int j = __ffs(m) - 1;
            if (cnt < MAXA) lp[cnt] = 32 * w + j;
            cnt++;
            m &= m - 1;
        }
    }
    g_cnt[t] = cnt < MAXA ? cnt : MAXA;
}

// ---------------- kernel 3: sparse gather (R4 L2-path version — measured fast) -----------
// 8192 CTAs of float4 L2 reads; measured 13.6 TB/s effective. The smem-staged variant
// lost twice (R3, R7) to latency exposure — do not revisit.
__global__ void __launch_bounds__(256) k_gather() {
    const int t  = blockIdx.x;
    const int n4 = blockIdx.y * 256 + threadIdx.x;      // float4 index into 2048 n
    const int c  = g_cnt[t];
    const int* __restrict__ lp = &g_idx[t * MAXA];

    float4 a0 = make_float4(0.f, 0.f, 0.f, 0.f);
    float4 a1 = make_float4(0.f, 0.f, 0.f, 0.f);
    float4 a2 = make_float4(0.f, 0.f, 0.f, 0.f);
    float4 a3 = make_float4(0.f, 0.f, 0.f, 0.f);

    int j = 0;
    for (; j + 4 <= c; j += 4) {
        const int p0 = lp[j], p1 = lp[j + 1], p2 = lp[j + 2], p3 = lp[j + 3];
        float4 w0 = ((const float4*)(g_WT + (size_t)p0 * N_POST))[n4];
        float4 w1 = ((const float4*)(g_WT + (size_t)p1 * N_POST))[n4];
        float4 w2 = ((const float4*)(g_WT + (size_t)p2 * N_POST))[n4];
        float4 w3 = ((const float4*)(g_WT + (size_t)p3 * N_POST))[n4];
        a0.x += w0.x; a0.y += w0.y; a0.z += w0.z; a0.w += w0.w;
        a1.x += w1.x; a1.y += w1.y; a1.z += w1.z; a1.w += w1.w;
        a2.x += w2.x; a2.y += w2.y; a2.z += w2.z; a2.w += w2.w;
        a3.x += w3.x; a3.y += w3.y; a3.z += w3.z; a3.w += w3.w;
    }
    for (; j < c; j++) {
        const int p0 = lp[j];
        float4 w0 = ((const float4*)(g_WT + (size_t)p0 * N_POST))[n4];
        a0.x += w0.x; a0.y += w0.y; a0.z += w0.z; a0.w += w0.w;
    }
    float4 s;
    s.x = (a0.x + a1.x) + (a2.x + a3.x);
    s.y = (a0.y + a1.y) + (a2.y + a3.y);
    s.z = (a0.z + a1.z) + (a2.z + a3.z);
    s.w = (a0.w + a1.w) + (a2.w + a3.w);
    ((float4*)(g_cur + (size_t)t * N_POST))[n4] = s;
}

// ---------------- kernel 4: LIF scan, spill-free static 3-stage pipeline (R4, 96.5us) ----
#define TT 16
__global__ void __launch_bounds__(32) k_lif_scan(float* __restrict__ out) {
    const int n = blockIdx.x * 32 + threadIdx.x;
    float* __restrict__ out_s = out + (size_t)n * SEQ_T;
    float* __restrict__ out_v = out + (size_t)N_POST * SEQ_T + (size_t)n * SEQ_T;

    const int NT = SEQ_T / TT;                          // 256 tiles
    float buf[3][TT];

#pragma unroll
    for (int s = 0; s < 3; s++)
#pragma unroll
        for (int k = 0; k < TT; k++)
            buf[s][k] = g_cur[(size_t)(s * TT + k) * N_POST + n];

    float v = 0.f;
    for (int base = 0; base < NT; base += 3) {
#pragma unroll
        for (int s = 0; s < 3; s++) {
            const int tile = base + s;
            if (tile < NT) {
                float sb[TT], vb[TT];
#pragma unroll
                for (int k = 0; k < TT; k++) {
                    v = v * DECAY + buf[s][k];
                    const bool f = (v >= V_TH);
                    sb[k] = f ? 1.f : 0.f;
                    v = f ? 0.f : v;
                    vb[k] = v;
                }
                if (tile + 3 < NT) {
#pragma unroll
                    for (int k = 0; k < TT; k++)
                        buf[s][k] = g_cur[(size_t)((tile + 3) * TT + k) * N_POST + n];
                }
                const size_t o4 = (size_t)tile * (TT / 4);
#pragma unroll
                for (int q = 0; q < TT / 4; q++) {
                    ((float4*)out_s)[o4 + q] =
                        make_float4(sb[4 * q], sb[4 * q + 1], sb[4 * q + 2], sb[4 * q + 3]);
                    ((float4*)out_v)[o4 + q] =
                        make_float4(vb[4 * q], vb[4 * q + 1], vb[4 * q + 2], vb[4 * q + 3]);
                }
            }
        }
    }
}

// ---------------- launch --------------------------------------------------------------
extern "C" void kernel_launch(void* const* d_in, const int* in_sizes, int n_in,
                              void* d_out, int out_size) {
    const float* stim = (const float*)d_in[0];   // [N_PRE, SEQ_T]
    const float* W    = (const float*)d_in[1];   // [N_POST, N_PRE]
    if (n_in >= 2 && in_sizes[0] == N_POST * N_PRE && in_sizes[1] == N_PRE * SEQ_T) {
        const float* tmp = stim; stim = W; W = tmp;
    }
    float* out = (float*)d_out;

    k_transpose<<<dim3(N_PRE / 32, N_POST / 32), dim3(32, 8)>>>(W);
    k_spike_bits<<<(32 * SEQ_T) / 256, 256>>>(stim);
    k_lists_from_bits<<<SEQ_T / 32, 32>>>();
    k_gather<<<dim3(SEQ_T, N_POST / 1024), 256>>>();
    k_lif_scan<<<N_POST / 32, 32>>>(out);
}

// round 9
// speedup vs baseline: 3.0927x; 1.0140x over previous
#include <cuda_runtime.h>
#include <cstdint>

#define N_PRE   1024
#define N_POST  2048
#define SEQ_T   4096
#define DECAY   0.9f
#define V_TH    1.0f
#define MAXA    192            // max actives/t (mean 102, sd 9.6; 192 ~ 9 sigma)

// ---------------- device scratch (no cudaMalloc allowed) --------------------------------
__device__ float    g_WT[N_PRE * (size_t)N_POST];       // W transposed: [p][n], 8 MB
__device__ uint32_t g_bits[32 * SEQ_T];                 // spike bitmask [w][t], 512 KB
__device__ int      g_cnt[SEQ_T];                       // active count per timestep
__device__ int      g_idx[SEQ_T * MAXA];                // active pre indices (ascending p)
__device__ float    g_cur[(size_t)SEQ_T * N_POST];      // currents [t][n], 32 MB

// ---------------- kernel 1: transpose W [n][p] -> WT [p][n] ------------------------------
__global__ void k_transpose(const float* __restrict__ W) {
    __shared__ float tile[32][33];
    const int p0 = blockIdx.x * 32;
    const int n0 = blockIdx.y * 32;
    const int tx = threadIdx.x, ty = threadIdx.y;   // block (32, 8)
#pragma unroll
    for (int i = 0; i < 32; i += 8)
        tile[ty + i][tx] = W[(size_t)(n0 + ty + i) * N_PRE + p0 + tx];
    __syncthreads();
#pragma unroll
    for (int i = 0; i < 32; i += 8)
        g_WT[(size_t)(p0 + ty + i) * N_POST + n0 + tx] = tile[tx][ty + i];
}

// ---------------- kernel 2a: stim -> bitmask, massively parallel -------------------------
__global__ void __launch_bounds__(256) k_spike_bits(const float* __restrict__ stim) {
    const int idx = blockIdx.x * 256 + threadIdx.x;     // 512 blocks x 256
    const int w = idx >> 12;                            // 0..31
    const int t = idx & (SEQ_T - 1);
    uint32_t m = 0;
#pragma unroll
    for (int j = 0; j < 32; j++)
        m |= (stim[(size_t)(32 * w + j) * SEQ_T + t] > 0.5f) ? (1u << j) : 0u;
    g_bits[w * SEQ_T + t] = m;
}

// ---------------- kernel 2b: bitmask -> index lists (cheap serial part) ------------------
__global__ void __launch_bounds__(32) k_lists_from_bits() {
    const int t = blockIdx.x * 32 + threadIdx.x;        // 128 blocks x 32
    uint32_t wbuf[32];
#pragma unroll
    for (int w = 0; w < 32; w++)
        wbuf[w] = g_bits[w * SEQ_T + t];                // coalesced at each w
    int cnt = 0;
    int* lp = &g_idx[t * MAXA];
#pragma unroll
    for (int w = 0; w < 32; w++) {
        uint32_t m = wbuf[w];
        while (m) {
            const int j = __ffs(m) - 1;
            if (cnt < MAXA) lp[cnt] = 32 * w + j;
            cnt++;
            m &= m - 1;
        }
    }
    g_cnt[t] = cnt < MAXA ? cnt : MAXA;
}

// ---------------- kernel 3: sparse gather (L2-path; 19 TB/s effective, near cache floor) --
__global__ void __launch_bounds__(256) k_gather() {
    const int t  = blockIdx.x;
    const int n4 = blockIdx.y * 256 + threadIdx.x;      // float4 index into 2048 n
    const int c  = g_cnt[t];
    const int* __restrict__ lp = &g_idx[t * MAXA];

    float4 a0 = make_float4(0.f, 0.f, 0.f, 0.f);
    float4 a1 = make_float4(0.f, 0.f, 0.f, 0.f);
    float4 a2 = make_float4(0.f, 0.f, 0.f, 0.f);
    float4 a3 = make_float4(0.f, 0.f, 0.f, 0.f);

    int j = 0;
    for (; j + 4 <= c; j += 4) {
        const int p0 = lp[j], p1 = lp[j + 1], p2 = lp[j + 2], p3 = lp[j + 3];
        float4 w0 = ((const float4*)(g_WT + (size_t)p0 * N_POST))[n4];
        float4 w1 = ((const float4*)(g_WT + (size_t)p1 * N_POST))[n4];
        float4 w2 = ((const float4*)(g_WT + (size_t)p2 * N_POST))[n4];
        float4 w3 = ((const float4*)(g_WT + (size_t)p3 * N_POST))[n4];
        a0.x += w0.x; a0.y += w0.y; a0.z += w0.z; a0.w += w0.w;
        a1.x += w1.x; a1.y += w1.y; a1.z += w1.z; a1.w += w1.w;
        a2.x += w2.x; a2.y += w2.y; a2.z += w2.z; a2.w += w2.w;
        a3.x += w3.x; a3.y += w3.y; a3.z += w3.z; a3.w += w3.w;
    }
    for (; j < c; j++) {
        const int p0 = lp[j];
        float4 w0 = ((const float4*)(g_WT + (size_t)p0 * N_POST))[n4];
        a0.x += w0.x; a0.y += w0.y; a0.z += w0.z; a0.w += w0.w;
    }
    float4 s;
    s.x = (a0.x + a1.x) + (a2.x + a3.x);
    s.y = (a0.y + a1.y) + (a2.y + a3.y);
    s.z = (a0.z + a1.z) + (a2.z + a3.z);
    s.w = (a0.w + a1.w) + (a2.w + a3.w);
    ((float4*)(g_cur + (size_t)t * N_POST))[n4] = s;
}

// ---------------- kernel 4: LIF scan v3 — no staging arrays, inline float4 stores --------
// R8's version kept sb[16]/vb[16] arrays whose live range crossed the chain loop; with
// regs capped at 72 they spilled to local (L1 14.6% busy, 754 cyc/tile vs ~260 model).
// v3 computes 4 steps, assembles the two float4s from named SSA values, stores
// immediately, and interleaves 4 refill LDGs per chunk. All indices compile-time.
#define TT 16
#define LIF_STEP(S, SPV, VV)                                \
    do {                                                    \
        v = v * DECAY + (S);                                \
        const bool _f = (v >= V_TH);                        \
        (SPV) = _f ? 1.f : 0.f;                             \
        v = _f ? 0.f : v;                                   \
        (VV) = v;                                           \
    } while (0)

__global__ void __launch_bounds__(32) k_lif_scan(float* __restrict__ out) {
    const int n = blockIdx.x * 32 + threadIdx.x;
    float* __restrict__ out_s = out + (size_t)n * SEQ_T;
    float* __restrict__ out_v = out + (size_t)N_POST * SEQ_T + (size_t)n * SEQ_T;

    const int NT = SEQ_T / TT;                          // 256 tiles
    float buf[3][TT];

#pragma unroll
    for (int s = 0; s < 3; s++)
#pragma unroll
        for (int k = 0; k < TT; k++)
            buf[s][k] = g_cur[(size_t)(s * TT + k) * N_POST + n];

    float v = 0.f;
    for (int base = 0; base < NT; base += 3) {
#pragma unroll
        for (int s = 0; s < 3; s++) {
            const int tile = base + s;
            if (tile < NT) {
                const bool refill = (tile + 3 < NT);
                const size_t rbase = (size_t)(tile + 3) * TT;
#pragma unroll
                for (int q = 0; q < TT / 4; q++) {
                    float s0, s1, s2, s3, v0, v1, v2, v3;
                    LIF_STEP(buf[s][4 * q + 0], s0, v0);
                    LIF_STEP(buf[s][4 * q + 1], s1, v1);
                    LIF_STEP(buf[s][4 * q + 2], s2, v2);
                    LIF_STEP(buf[s][4 * q + 3], s3, v3);
                    ((float4*)out_s)[tile * (TT / 4) + q] = make_float4(s0, s1, s2, s3);
                    ((float4*)out_v)[tile * (TT / 4) + q] = make_float4(v0, v1, v2, v3);
                    // interleaved refill of the 4 slots just consumed (for tile+3)
                    if (refill) {
                        buf[s][4 * q + 0] = g_cur[(rbase + 4 * q + 0) * N_POST + n];
                        buf[s][4 * q + 1] = g_cur[(rbase + 4 * q + 1) * N_POST + n];
                        buf[s][4 * q + 2] = g_cur[(rbase + 4 * q + 2) * N_POST + n];
                        buf[s][4 * q + 3] = g_cur[(rbase + 4 * q + 3) * N_POST + n];
                    }
                }
            }
        }
    }
}

// ---------------- launch --------------------------------------------------------------
extern "C" void kernel_launch(void* const* d_in, const int* in_sizes, int n_in,
                              void* d_out, int out_size) {
    const float* stim = (const float*)d_in[0];   // [N_PRE, SEQ_T]
    const float* W    = (const float*)d_in[1];   // [N_POST, N_PRE]
    if (n_in >= 2 && in_sizes[0] == N_POST * N_PRE && in_sizes[1] == N_PRE * SEQ_T) {
        const float* tmp = stim; stim = W; W = tmp;
    }
    float* out = (float*)d_out;

    k_transpose<<<dim3(N_PRE / 32, N_POST / 32), dim3(32, 8)>>>(W);
    k_spike_bits<<<(32 * SEQ_T) / 256, 256>>>(stim);
    k_lists_from_bits<<<SEQ_T / 32, 32>>>();
    k_gather<<<dim3(SEQ_T, N_POST / 1024), 256>>>();
    k_lif_scan<<<N_POST / 32, 32>>>(out);
}

// round 12
// speedup vs baseline: 3.6143x; 1.1686x over previous
#include <cuda_runtime.h>
#include <cstdint>

#define N_PRE   1024
#define N_POST  2048
#define SEQ_T   4096
#define DECAY   0.9f
#define V_TH    1.0f
#define MAXA    192            // max actives/t (mean 102, sd 9.6; 192 ~ 9 sigma)

// ---------------- device scratch (no cudaMalloc allowed) --------------------------------
__device__ float    g_WT[N_PRE * (size_t)N_POST];       // W transposed: [p][n], 8 MB
__device__ uint32_t g_bits[32 * SEQ_T];                 // spike bitmask [w][t], 512 KB
__device__ int      g_cnt[SEQ_T];                       // active count per timestep
__device__ int      g_idx[SEQ_T * MAXA];                // active pre indices (ascending p)
__device__ float    g_cur[(size_t)SEQ_T * N_POST];      // currents [t][n], 32 MB

// ---------------- kernel 1: transpose W [n][p] -> WT [p][n] ------------------------------
__global__ void k_transpose(const float* __restrict__ W) {
    __shared__ float tile[32][33];
    const int p0 = blockIdx.x * 32;
    const int n0 = blockIdx.y * 32;
    const int tx = threadIdx.x, ty = threadIdx.y;   // block (32, 8)
#pragma unroll
    for (int i = 0; i < 32; i += 8)
        tile[ty + i][tx] = W[(size_t)(n0 + ty + i) * N_PRE + p0 + tx];
    __syncthreads();
#pragma unroll
    for (int i = 0; i < 32; i += 8)
        g_WT[(size_t)(p0 + ty + i) * N_POST + n0 + tx] = tile[tx][ty + i];
}

// ---------------- kernel 2a: stim -> bitmask, massively parallel -------------------------
__global__ void __launch_bounds__(256) k_spike_bits(const float* __restrict__ stim) {
    const int idx = blockIdx.x * 256 + threadIdx.x;     // 512 blocks x 256
    const int w = idx >> 12;                            // 0..31
    const int t = idx & (SEQ_T - 1);
    uint32_t m = 0;
#pragma unroll
    for (int j = 0; j < 32; j++)
        m |= (stim[(size_t)(32 * w + j) * SEQ_T + t] > 0.5f) ? (1u << j) : 0u;
    g_bits[w * SEQ_T + t] = m;
}

// ---------------- kernel 2b: bitmask -> index lists --------------------------------------
__global__ void __launch_bounds__(32) k_lists_from_bits() {
    const int t = blockIdx.x * 32 + threadIdx.x;        // 128 blocks x 32
    uint32_t wbuf[32];
#pragma unroll
    for (int w = 0; w < 32; w++)
        wbuf[w] = g_bits[w * SEQ_T + t];                // coalesced at each w
    int cnt = 0;
    int* lp = &g_idx[t * MAXA];
#pragma unroll
    for (int w = 0; w < 32; w++) {
        uint32_t m = wbuf[w];
        while (m) {
            const int j = __ffs(m) - 1;
            if (cnt < MAXA) lp[cnt] = 32 * w + j;
            cnt++;
            m &= m - 1;
        }
    }
    g_cnt[t] = cnt < MAXA ? cnt : MAXA;
}

// ---------------- kernel 3: sparse gather (L2-path; ~19 TB/s effective, at cache floor) ---
__global__ void __launch_bounds__(256) k_gather() {
    const int t  = blockIdx.x;
    const int n4 = blockIdx.y * 256 + threadIdx.x;      // float4 index into 2048 n
    const int c  = g_cnt[t];
    const int* __restrict__ lp = &g_idx[t * MAXA];

    float4 a0 = make_float4(0.f, 0.f, 0.f, 0.f);
    float4 a1 = make_float4(0.f, 0.f, 0.f, 0.f);
    float4 a2 = make_float4(0.f, 0.f, 0.f, 0.f);
    float4 a3 = make_float4(0.f, 0.f, 0.f, 0.f);

    int j = 0;
    for (; j + 4 <= c; j += 4) {
        const int p0 = lp[j], p1 = lp[j + 1], p2 = lp[j + 2], p3 = lp[j + 3];
        float4 w0 = ((const float4*)(g_WT + (size_t)p0 * N_POST))[n4];
        float4 w1 = ((const float4*)(g_WT + (size_t)p1 * N_POST))[n4];
        float4 w2 = ((const float4*)(g_WT + (size_t)p2 * N_POST))[n4];
        float4 w3 = ((const float4*)(g_WT + (size_t)p3 * N_POST))[n4];
        a0.x += w0.x; a0.y += w0.y; a0.z += w0.z; a0.w += w0.w;
        a1.x += w1.x; a1.y += w1.y; a1.z += w1.z; a1.w += w1.w;
        a2.x += w2.x; a2.y += w2.y; a2.z += w2.z; a2.w += w2.w;
        a3.x += w3.x; a3.y += w3.y; a3.z += w3.z; a3.w += w3.w;
    }
    for (; j < c; j++) {
        const int p0 = lp[j];
        float4 w0 = ((const float4*)(g_WT + (size_t)p0 * N_POST))[n4];
        a0.x += w0.x; a0.y += w0.y; a0.z += w0.z; a0.w += w0.w;
    }
    float4 s;
    s.x = (a0.x + a1.x) + (a2.x + a3.x);
    s.y = (a0.y + a1.y) + (a2.y + a3.y);
    s.z = (a0.z + a1.z) + (a2.z + a3.z);
    s.w = (a0.w + a1.w) + (a2.w + a3.w);
    ((float4*)(g_cur + (size_t)t * N_POST))[n4] = s;
}

// ---------------- kernel 4: LIF scan, speculative t-chunking -----------------------------
// 4 chunks of 1024 per neuron. Chunk 0 starts exactly (v=0 at t=0). Chunks 1-3 start
// from v=0 at t0-384 and run a 384-step warmup (no stores): the start error decays
// 0.9^k (<1e-17 by output), and common spikes reset both trajectories to exactly 0.0
// (bit-exact merge every ~5 steps). Serial chain per neuron drops 4096 -> 1408 steps.
// 8192 chains = 256 blocks x 32 threads. Compile-time buffer indices throughout.
#define TT  16
#define CH  1024
#define WU  384
#define LIF_STEP(S, SPV, VV)                                \
    do {                                                    \
        v = v * DECAY + (S);                                \
        const bool _f = (v >= V_TH);                        \
        (SPV) = _f ? 1.f : 0.f;                             \
        v = _f ? 0.f : v;                                   \
        (VV) = v;                                           \
    } while (0)
#define LIF_WU(S)                                           \
    do {                                                    \
        v = v * DECAY + (S);                                \
        v = (v >= V_TH) ? 0.f : v;                          \
    } while (0)

__global__ void __launch_bounds__(32) k_lif_scan(float* __restrict__ out) {
    const int bq = blockIdx.x;                          // 0..255
    const int q  = bq >> 6;                             // chunk 0..3
    const int nb = bq & 63;                             // neuron block 0..63
    const int n  = nb * 32 + threadIdx.x;
    const int t0 = q * CH;

    const float* __restrict__ cur = g_cur + n;          // stride N_POST over t
    float* __restrict__ out_s = out + (size_t)n * SEQ_T + t0;
    float* __restrict__ out_v = out + (size_t)N_POST * SEQ_T + (size_t)n * SEQ_T + t0;

    float v = 0.f;

    // ---- speculative warmup: [t0-WU, t0), no stores, 2-buffer ping-pong ----
    if (q > 0) {
        const int w0 = t0 - WU;                         // multiple of TT
        float wb[2][TT];
#pragma unroll
        for (int k = 0; k < TT; k++) wb[0][k] = cur[(size_t)(w0 + k) * N_POST];
#pragma unroll
        for (int k = 0; k < TT; k++) wb[1][k] = cur[(size_t)(w0 + TT + k) * N_POST];
        const int WT_ = WU / TT;                        // 24 tiles
        for (int tp = 0; tp < WT_; tp += 2) {
#pragma unroll
            for (int k = 0; k < TT; k++) LIF_WU(wb[0][k]);
            if (tp + 2 < WT_) {
#pragma unroll
                for (int k = 0; k < TT; k++)
                    wb[0][k] = cur[(size_t)(w0 + (tp + 2) * TT + k) * N_POST];
            }
#pragma unroll
            for (int k = 0; k < TT; k++) LIF_WU(wb[1][k]);
            if (tp + 3 < WT_) {
#pragma unroll
                for (int k = 0; k < TT; k++)
                    wb[1][k] = cur[(size_t)(w0 + (tp + 3) * TT + k) * N_POST];
            }
        }
    }

    // ---- output phase: [t0, t0+CH), 3-stage pipeline, inline float4 stores ----
    const int NT = CH / TT;                             // 64 tiles
    float buf[3][TT];
#pragma unroll
    for (int s = 0; s < 3; s++)
#pragma unroll
        for (int k = 0; k < TT; k++)
            buf[s][k] = cur[(size_t)(t0 + s * TT + k) * N_POST];

    for (int base = 0; base < NT; base += 3) {
#pragma unroll
        for (int s = 0; s < 3; s++) {
            const int tile = base + s;
            if (tile < NT) {
                const bool refill = (tile + 3 < NT);
                const size_t rbase = (size_t)(t0 + (tile + 3) * TT);
#pragma unroll
                for (int c4 = 0; c4 < TT / 4; c4++) {
                    float s0, s1, s2, s3, v0, v1, v2, v3;
                    LIF_STEP(buf[s][4 * c4 + 0], s0, v0);
                    LIF_STEP(buf[s][4 * c4 + 1], s1, v1);
                    LIF_STEP(buf[s][4 * c4 + 2], s2, v2);
                    LIF_STEP(buf[s][4 * c4 + 3], s3, v3);
                    ((float4*)out_s)[tile * (TT / 4) + c4] = make_float4(s0, s1, s2, s3);
                    ((float4*)out_v)[tile * (TT / 4) + c4] = make_float4(v0, v1, v2, v3);
                    if (refill) {
                        buf[s][4 * c4 + 0] = cur[(rbase + 4 * c4 + 0) * N_POST];
                        buf[s][4 * c4 + 1] = cur[(rbase + 4 * c4 + 1) * N_POST];
                        buf[s][4 * c4 + 2] = cur[(rbase + 4 * c4 + 2) * N_POST];
                        buf[s][4 * c4 + 3] = cur[(rbase + 4 * c4 + 3) * N_POST];
                    }
                }
            }
        }
    }
}

// ---------------- launch --------------------------------------------------------------
extern "C" void kernel_launch(void* const* d_in, const int* in_sizes, int n_in,
                              void* d_out, int out_size) {
    const float* stim = (const float*)d_in[0];   // [N_PRE, SEQ_T]
    const float* W    = (const float*)d_in[1];   // [N_POST, N_PRE]
    if (n_in >= 2 && in_sizes[0] == N_POST * N_PRE && in_sizes[1] == N_PRE * SEQ_T) {
        const float* tmp = stim; stim = W; W = tmp;
    }
    float* out = (float*)d_out;

    k_transpose<<<dim3(N_PRE / 32, N_POST / 32), dim3(32, 8)>>>(W);
    k_spike_bits<<<(32 * SEQ_T) / 256, 256>>>(stim);
    k_lists_from_bits<<<SEQ_T / 32, 32>>>();
    k_gather<<<dim3(SEQ_T, N_POST / 1024), 256>>>();
    k_lif_scan<<<(N_POST / 32) * (SEQ_T / CH), 32>>>(out);
}